// round 16
// baseline (speedup 1.0000x reference)
#include <cuda_runtime.h>
#include <cuda_fp16.h>
#include <cstdint>

#define D_MODEL   1024
#define NUM_HEADS 16
#define HEAD_DIM  64
#define D_FF      4096
#define B_        2
#define S_        2048
#define ROWS      (B_ * S_)   // 4096
#define QKV_N     (3 * D_MODEL)

// ---------------------------------------------------------------------------
// Scratch (device globals; no allocation allowed)
// ---------------------------------------------------------------------------
__device__ __half g_xh  [ROWS * D_MODEL];
__device__ __half g_qkv [ROWS * QKV_N];
__device__ __half g_attn[ROWS * D_MODEL];
__device__ float  g_proj[ROWS * D_MODEL];
__device__ float  g_x1  [ROWS * D_MODEL];
__device__ __half g_x1h [ROWS * D_MODEL];
__device__ __half g_ff1 [ROWS * D_FF];
__device__ float  g_ff2 [ROWS * D_MODEL];
__device__ __half g_wqkvt[QKV_N * D_MODEL];
__device__ __half g_wot  [D_MODEL * D_MODEL];
__device__ __half g_w1t  [D_FF * D_MODEL];
__device__ __half g_w2t  [D_MODEL * D_FF];
__device__ float  g_bqkv [QKV_N];

__device__ __forceinline__ uint32_t smem_u32(const void* p) {
    uint32_t a;
    asm("{ .reg .u64 t; cvta.to.shared.u64 t, %1; cvt.u32.u64 %0, t; }"
        : "=r"(a) : "l"(p));
    return a;
}
// fp16 mma m16n8k16, fp32 accum
__device__ __forceinline__ void mma_f16(float* d, const uint32_t* a,
                                        uint32_t b0, uint32_t b1) {
    asm volatile(
        "mma.sync.aligned.m16n8k16.row.col.f32.f16.f16.f32 "
        "{%0,%1,%2,%3}, {%4,%5,%6,%7}, {%8,%9}, {%0,%1,%2,%3};"
        : "+f"(d[0]), "+f"(d[1]), "+f"(d[2]), "+f"(d[3])
        : "r"(a[0]), "r"(a[1]), "r"(a[2]), "r"(a[3]), "r"(b0), "r"(b1));
}
#define LDSM_X4(R0, R1, R2, R3, saddr) \
    asm volatile("ldmatrix.sync.aligned.m8n8.x4.shared.b16 {%0,%1,%2,%3}, [%4];" \
        : "=r"(R0), "=r"(R1), "=r"(R2), "=r"(R3) : "r"(saddr))
#define CP16(dst, src) \
    asm volatile("cp.async.cg.shared.global [%0], [%1], 16;" \
                 :: "r"(dst), "l"(src) : "memory")
#define CP_COMMIT() asm volatile("cp.async.commit_group;" ::: "memory")
#define CP_WAITG1() asm volatile("cp.async.wait_group 1;" ::: "memory")

__device__ __forceinline__ uint32_t pack_h2(float lo, float hi) {
    __half2 h = __floats2half2_rn(lo, hi);
    return *(uint32_t*)&h;
}

// ---------------------------------------------------------------------------
// Weight prep
// ---------------------------------------------------------------------------
__global__ __launch_bounds__(256)
void transpose3_kernel(const float* __restrict__ wq, const float* __restrict__ wk,
                       const float* __restrict__ wv, __half* __restrict__ out)
{
    __shared__ float t[32][33];
    const float* W = (blockIdx.z == 0) ? wq : (blockIdx.z == 1) ? wk : wv;
    __half* Wt = out + (size_t)blockIdx.z * D_MODEL * D_MODEL;
    const int bn = blockIdx.x * 32;
    const int bk = blockIdx.y * 32;
    const int x = threadIdx.x & 31;
    const int y = (threadIdx.x >> 5) * 4;
    #pragma unroll
    for (int i = 0; i < 4; i++)
        t[y + i][x] = W[(size_t)(bk + y + i) * D_MODEL + bn + x];
    __syncthreads();
    #pragma unroll
    for (int i = 0; i < 4; i++)
        Wt[(size_t)(bn + y + i) * D_MODEL + bk + x] = __float2half(t[x][y + i]);
}

__global__ __launch_bounds__(256)
void transpose_h_kernel(const float* __restrict__ W, __half* __restrict__ Wt,
                        int Kd, int N)
{
    __shared__ float t[32][33];
    const int bn = blockIdx.x * 32;
    const int bk = blockIdx.y * 32;
    const int x = threadIdx.x & 31;
    const int y = (threadIdx.x >> 5) * 4;
    #pragma unroll
    for (int i = 0; i < 4; i++)
        t[y + i][x] = W[(size_t)(bk + y + i) * N + bn + x];
    __syncthreads();
    #pragma unroll
    for (int i = 0; i < 4; i++)
        Wt[(size_t)(bn + y + i) * Kd + bk + x] = __float2half(t[x][y + i]);
}

// Fused prep: blocks [0,2048) convert x -> xh; blocks [2048,2060) pack bias.
__global__ __launch_bounds__(256)
void prep_kernel(const float* __restrict__ in, __half* __restrict__ out,
                 const float* __restrict__ bq, const float* __restrict__ bk,
                 const float* __restrict__ bv, float* __restrict__ ob)
{
    const int bx = blockIdx.x;
    if (bx < 2048) {
        const int i = bx * 256 + threadIdx.x;
        float4 a = ((const float4*)in)[2 * i];
        float4 b = ((const float4*)in)[2 * i + 1];
        uint4 o;
        o.x = pack_h2(a.x, a.y); o.y = pack_h2(a.z, a.w);
        o.z = pack_h2(b.x, b.y); o.w = pack_h2(b.z, b.w);
        ((uint4*)out)[i] = o;
    } else {
        const int i = (bx - 2048) * 256 + threadIdx.x;
        float v = (i < 1024) ? bq[i] : (i < 2048) ? bk[i - 1024] : bv[i - 2048];
        ob[i] = v;
    }
}

// ---------------------------------------------------------------------------
// fp16 mma.sync GEMM (R13 3-stage pipeline — unchanged, proven).
// ---------------------------------------------------------------------------
#define GSTR 36
#define GOP  (128 * GSTR)
#define STGW (2 * GOP)
#define GEMM_SMEM_BYTES (3 * STGW * 4)    // 110592

__global__ __launch_bounds__(128)
void gemm_f16(const __half* __restrict__ A,
              const __half* __restrict__ Bt,
              const float* __restrict__ bias,
              void* __restrict__ Cv,
              int Kd, int N, int mode)
{
    extern __shared__ uint32_t smg[];
    const uint32_t sbase = smem_u32(smg);

    const int tid  = threadIdx.x;
    const int lane = tid & 31;
    const int wid  = tid >> 5;
    const int g = lane >> 2;
    const int t = lane & 3;
    const int wm = wid & 1;
    const int wn = wid >> 1;
    const int row0 = blockIdx.y * 128;
    const int col0 = blockIdx.x * 128;

    float acc[4][8][4];
    #pragma unroll
    for (int mi = 0; mi < 4; mi++)
        #pragma unroll
        for (int ni = 0; ni < 8; ni++)
            #pragma unroll
            for (int j = 0; j < 4; j++) acc[mi][ni][j] = 0.f;

    uint32_t sdst[8];
    const __half* aP[8];
    const __half* bP[8];
    #pragma unroll
    for (int i = 0; i < 8; i++) {
        const int slot = tid + i * 128;
        const int r = slot >> 3, q = slot & 7;
        sdst[i] = (uint32_t)(r * GSTR + q * 4) * 4u;
        aP[i] = A  + (size_t)(row0 + r) * Kd + q * 8;
        bP[i] = Bt + (size_t)(col0 + r) * Kd + q * 8;
    }

    const int lane7 = lane & 7;
    const uint32_t aRow  = (uint32_t)(wm * 64 + lane7 + (lane & 8));
    const uint32_t aColW = (uint32_t)((lane >> 4) * 4);
    const uint32_t aOffB = (aRow * GSTR + aColW) * 4u;
    const uint32_t bRow  = (uint32_t)(wn * 64 + lane7 + ((lane >> 4) & 1) * 8);
    const uint32_t bColW = (uint32_t)(((lane >> 3) & 1) * 4);
    const uint32_t bOffB = (bRow * GSTR + bColW) * 4u + GOP * 4u;

    const int NC = Kd >> 6;

    #pragma unroll
    for (int i = 0; i < 8; i++) {
        CP16(sbase + sdst[i], aP[i]);
        CP16(sbase + GOP * 4u + sdst[i], bP[i]);
    }
    CP_COMMIT();
    {
        const uint32_t st = (uint32_t)STGW * 4u;
        #pragma unroll
        for (int i = 0; i < 8; i++) {
            CP16(sbase + st + sdst[i], aP[i] + 64);
            CP16(sbase + st + GOP * 4u + sdst[i], bP[i] + 64);
        }
        CP_COMMIT();
    }

    for (int c = 0; c < NC; c++) {
        CP_WAITG1();
        __syncthreads();

        const uint32_t stg = sbase + (uint32_t)(c % 3) * ((uint32_t)STGW * 4u);
        const uint32_t aBase = stg + aOffB;
        const uint32_t bBase = stg + bOffB;

        #pragma unroll
        for (int ks = 0; ks < 4; ks++) {
            const uint32_t kOff = (uint32_t)(ks * 8) * 4u;
            uint32_t af[4][4];
            #pragma unroll
            for (int mi = 0; mi < 4; mi++) {
                LDSM_X4(af[mi][0], af[mi][1], af[mi][2], af[mi][3],
                        aBase + (uint32_t)(mi * 16 * GSTR) * 4u + kOff);
            }
            uint32_t bf[8][2];
            #pragma unroll
            for (int pr = 0; pr < 4; pr++) {
                LDSM_X4(bf[2 * pr][0], bf[2 * pr][1], bf[2 * pr + 1][0], bf[2 * pr + 1][1],
                        bBase + (uint32_t)(pr * 16 * GSTR) * 4u + kOff);
            }
            #pragma unroll
            for (int ni = 0; ni < 8; ni++)
                #pragma unroll
                for (int mi = 0; mi < 4; mi++)
                    mma_f16(acc[mi][ni], af[mi], bf[ni][0], bf[ni][1]);
        }

        if (c + 2 < NC) {
            const int ko = (c + 2) * 64;
            const uint32_t st = (uint32_t)((c + 2) % 3) * ((uint32_t)STGW * 4u);
            #pragma unroll
            for (int i = 0; i < 8; i++) {
                CP16(sbase + st + sdst[i], aP[i] + ko);
                CP16(sbase + st + GOP * 4u + sdst[i], bP[i] + ko);
            }
            CP_COMMIT();
        }
    }

    #pragma unroll
    for (int mi = 0; mi < 4; mi++) {
        const int r0 = row0 + wm * 64 + mi * 16 + g;
        #pragma unroll
        for (int ni = 0; ni < 8; ni++) {
            const int col = col0 + wn * 64 + ni * 8 + 2 * t;
            float2 bb = *(const float2*)&bias[col];
            float v00 = acc[mi][ni][0] + bb.x;
            float v01 = acc[mi][ni][1] + bb.y;
            float v10 = acc[mi][ni][2] + bb.x;
            float v11 = acc[mi][ni][3] + bb.y;
            if (mode == 0) {
                float* C = (float*)Cv;
                float2 o0 = {v00, v01}, o1 = {v10, v11};
                *(float2*)&C[(size_t)r0 * N + col]       = o0;
                *(float2*)&C[(size_t)(r0 + 8) * N + col] = o1;
            } else {
                if (mode == 1) {
                    v00 = fmaxf(v00, 0.f); v01 = fmaxf(v01, 0.f);
                    v10 = fmaxf(v10, 0.f); v11 = fmaxf(v11, 0.f);
                }
                __half* C = (__half*)Cv;
                *(uint32_t*)&C[(size_t)r0 * N + col]       = pack_h2(v00, v01);
                *(uint32_t*)&C[(size_t)(r0 + 8) * N + col] = pack_h2(v10, v11);
            }
        }
    }
}

// ---------------------------------------------------------------------------
// fp16 flash attention v4: 128 q/CTA, 32 q/warp, DOUBLE-BUFFERED K/V tiles.
// Per tile: one __syncthreads; next tile's LDG/STS overlap current compute.
// Dynamic SMEM layout (words):
//   Qs [0, 5632)                      128 x 44
//   Ks [5632 + bi*2816, +2816)        2 x (64 x 44)
//   VT [11264 + bi*2304, +2304)       2 x (32 x 72)
//   msb[15872 + bi*2 + w]             2 x 2
// Total 15876 words = 63504 B; 2 CTAs/SM.
// ---------------------------------------------------------------------------
#define ASTR 44
#define VSTR 72
#define AQ_OFF  0
#define AK_OFF  5632
#define AV_OFF  11264
#define AM_OFF  15872
#define ATTN_SMEM_BYTES (15876 * 4)

__global__ __launch_bounds__(128)
void attn_f16(const __half* __restrict__ QKV,
              const int*   __restrict__ mask,
              __half* __restrict__ O)
{
    extern __shared__ uint32_t sm[];
    uint32_t* Qs = sm + AQ_OFF;

    const int b  = blockIdx.z;
    const int h  = blockIdx.y;
    const int q0 = blockIdx.x * 128;
    const int tid  = threadIdx.x;
    const int lane = tid & 31;
    const int wid  = tid >> 5;
    const int g = lane >> 2;
    const int t = lane & 3;

    const int qc = h * HEAD_DIM;
    const int kc = D_MODEL + h * HEAD_DIM;
    const int vc = 2 * D_MODEL + h * HEAD_DIM;

    const int vj = tid & 31;
    const int vdh = (tid >> 5) * 16;

    // ---- tile loader (K, V-zip, mask) into buffer bi ----
    auto load_tile = [&](int kt, int bi) {
        uint32_t* Ks = sm + AK_OFF + bi * 2816;
        uint32_t* VT = sm + AV_OFF + bi * 2304;
        #pragma unroll
        for (int i = 0; i < 4; i++) {
            const int slot = tid + i * 128;
            const int r = slot >> 3, q8 = slot & 7;
            uint4 v = *(const uint4*)(QKV + (size_t)(b * S_ + kt + r) * QKV_N + kc + q8 * 8);
            *(uint4*)&Ks[r * ASTR + q8 * 4] = v;
        }
        {
            const __half* v0p = QKV + (size_t)(b * S_ + kt + 2 * vj) * QKV_N + vc + vdh;
            const __half* v1p = v0p + QKV_N;
            uint4 r0a = *(const uint4*)(v0p);
            uint4 r0b = *(const uint4*)(v0p + 8);
            uint4 r1a = *(const uint4*)(v1p);
            uint4 r1b = *(const uint4*)(v1p + 8);
            uint32_t* dst = &VT[vj * VSTR + vdh];
            uint4 z;
            z.x = __byte_perm(r0a.x, r1a.x, 0x5410);
            z.y = __byte_perm(r0a.x, r1a.x, 0x7632);
            z.z = __byte_perm(r0a.y, r1a.y, 0x5410);
            z.w = __byte_perm(r0a.y, r1a.y, 0x7632);
            *(uint4*)dst = z;
            z.x = __byte_perm(r0a.z, r1a.z, 0x5410);
            z.y = __byte_perm(r0a.z, r1a.z, 0x7632);
            z.z = __byte_perm(r0a.w, r1a.w, 0x5410);
            z.w = __byte_perm(r0a.w, r1a.w, 0x7632);
            *(uint4*)(dst + 4) = z;
            z.x = __byte_perm(r0b.x, r1b.x, 0x5410);
            z.y = __byte_perm(r0b.x, r1b.x, 0x7632);
            z.z = __byte_perm(r0b.y, r1b.y, 0x5410);
            z.w = __byte_perm(r0b.y, r1b.y, 0x7632);
            *(uint4*)(dst + 8) = z;
            z.x = __byte_perm(r0b.z, r1b.z, 0x5410);
            z.y = __byte_perm(r0b.z, r1b.z, 0x7632);
            z.z = __byte_perm(r0b.w, r1b.w, 0x5410);
            z.w = __byte_perm(r0b.w, r1b.w, 0x7632);
            *(uint4*)(dst + 12) = z;
        }
        if (tid < 64) {
            const int mv = mask[b * S_ + kt + tid];
            const uint32_t bits = __ballot_sync(0xffffffffu, mv != 0);
            if (lane == 0) sm[AM_OFF + bi * 2 + wid] = bits;
        }
    };

    // ---- Stage Q tile, extract fragments ----
    #pragma unroll
    for (int i = 0; i < 8; i++) {
        const int slot = tid + i * 128;
        const int r = slot >> 3, q8 = slot & 7;
        uint4 v = *(const uint4*)(QKV + (size_t)(b * S_ + q0 + r) * QKV_N + qc + q8 * 8);
        *(uint4*)&Qs[r * ASTR + q8 * 4] = v;
    }
    load_tile(0, 0);
    __syncthreads();

    uint32_t qf[2][4][4];
    #pragma unroll
    for (int mi = 0; mi < 2; mi++) {
        const int mrow = wid * 32 + mi * 16 + g;
        #pragma unroll
        for (int ks = 0; ks < 4; ks++) {
            qf[mi][ks][0] = Qs[mrow * ASTR + ks * 8 + t];
            qf[mi][ks][1] = Qs[(mrow + 8) * ASTR + ks * 8 + t];
            qf[mi][ks][2] = Qs[mrow * ASTR + ks * 8 + 4 + t];
            qf[mi][ks][3] = Qs[(mrow + 8) * ASTR + ks * 8 + 4 + t];
        }
    }
    // NOTE: Qs is not reused, so no extra sync needed here.

    float o[2][8][4];
    #pragma unroll
    for (int mi = 0; mi < 2; mi++)
        #pragma unroll
        for (int ni = 0; ni < 8; ni++)
            #pragma unroll
            for (int j = 0; j < 4; j++) o[mi][ni][j] = 0.f;
    float mx[2][2] = {{-1e30f, -1e30f}, {-1e30f, -1e30f}};
    float lv[2][2] = {{0.f, 0.f}, {0.f, 0.f}};

    for (int kt = 0; kt < S_; kt += 64) {
        const int bi = (kt >> 6) & 1;
        // Prefetch next tile into the other buffer (overlaps compute below)
        if (kt + 64 < S_) load_tile(kt + 64, bi ^ 1);

        const uint32_t* Ks = sm + AK_OFF + bi * 2816;
        const uint32_t* VT = sm + AV_OFF + bi * 2304;
        const uint32_t mw0 = sm[AM_OFF + bi * 2];
        const uint32_t mw1 = sm[AM_OFF + bi * 2 + 1];
        const bool allon = (mw0 & mw1) == 0xffffffffu;

        // S = Q @ K^T
        float s[2][8][4];
        #pragma unroll
        for (int mi = 0; mi < 2; mi++)
            #pragma unroll
            for (int ni = 0; ni < 8; ni++)
                #pragma unroll
                for (int j = 0; j < 4; j++) s[mi][ni][j] = 0.f;

        #pragma unroll
        for (int ks = 0; ks < 4; ks++) {
            #pragma unroll
            for (int ni = 0; ni < 8; ni++) {
                const int n0 = ni * 8 + g;
                const uint32_t b0 = Ks[n0 * ASTR + ks * 8 + t];
                const uint32_t b1 = Ks[n0 * ASTR + ks * 8 + 4 + t];
                mma_f16(s[0][ni], qf[0][ks], b0, b1);
                mma_f16(s[1][ni], qf[1][ks], b0, b1);
            }
        }

        // scale + mask + online softmax
        bool k0a[8], k1a[8];
        if (!allon) {
            #pragma unroll
            for (int ni = 0; ni < 8; ni++) {
                const uint32_t word = (ni < 4) ? mw0 : mw1;
                const int shift = (ni & 3) * 8 + 2 * t;
                k0a[ni] = (word >> shift) & 1u;
                k1a[ni] = (word >> (shift + 1)) & 1u;
            }
        }

        #pragma unroll
        for (int mi = 0; mi < 2; mi++) {
            float rmax0 = -1e30f, rmax1 = -1e30f;
            #pragma unroll
            for (int ni = 0; ni < 8; ni++) {
                float v0 = s[mi][ni][0] * 0.125f;
                float v1 = s[mi][ni][1] * 0.125f;
                float v2 = s[mi][ni][2] * 0.125f;
                float v3 = s[mi][ni][3] * 0.125f;
                if (!allon) {
                    if (!k0a[ni]) { v0 = -1e9f; v2 = -1e9f; }
                    if (!k1a[ni]) { v1 = -1e9f; v3 = -1e9f; }
                }
                s[mi][ni][0] = v0; s[mi][ni][1] = v1;
                s[mi][ni][2] = v2; s[mi][ni][3] = v3;
                rmax0 = fmaxf(rmax0, fmaxf(v0, v1));
                rmax1 = fmaxf(rmax1, fmaxf(v2, v3));
            }
            rmax0 = fmaxf(rmax0, __shfl_xor_sync(0xffffffffu, rmax0, 1));
            rmax0 = fmaxf(rmax0, __shfl_xor_sync(0xffffffffu, rmax0, 2));
            rmax1 = fmaxf(rmax1, __shfl_xor_sync(0xffffffffu, rmax1, 1));
            rmax1 = fmaxf(rmax1, __shfl_xor_sync(0xffffffffu, rmax1, 2));

            const float mn0 = fmaxf(mx[mi][0], rmax0);
            const float mn1 = fmaxf(mx[mi][1], rmax1);
            const float c0 = __expf(mx[mi][0] - mn0);
            const float c1 = __expf(mx[mi][1] - mn1);

            float rs0 = 0.f, rs1 = 0.f;
            #pragma unroll
            for (int ni = 0; ni < 8; ni++) {
                float p0 = __expf(s[mi][ni][0] - mn0);
                float p1 = __expf(s[mi][ni][1] - mn0);
                float p2 = __expf(s[mi][ni][2] - mn1);
                float p3 = __expf(s[mi][ni][3] - mn1);
                s[mi][ni][0] = p0; s[mi][ni][1] = p1;
                s[mi][ni][2] = p2; s[mi][ni][3] = p3;
                rs0 += p0 + p1;
                rs1 += p2 + p3;
            }
            rs0 += __shfl_xor_sync(0xffffffffu, rs0, 1);
            rs0 += __shfl_xor_sync(0xffffffffu, rs0, 2);
            rs1 += __shfl_xor_sync(0xffffffffu, rs1, 1);
            rs1 += __shfl_xor_sync(0xffffffffu, rs1, 2);

            lv[mi][0] = lv[mi][0] * c0 + rs0;
            lv[mi][1] = lv[mi][1] * c1 + rs1;
            #pragma unroll
            for (int ni = 0; ni < 8; ni++) {
                o[mi][ni][0] *= c0; o[mi][ni][1] *= c0;
                o[mi][ni][2] *= c1; o[mi][ni][3] *= c1;
            }
            mx[mi][0] = mn0; mx[mi][1] = mn1;
        }

        // O += P @ V (register P)
        #pragma unroll
        for (int ks = 0; ks < 4; ks++) {
            uint32_t a0[4], a1[4];
            a0[0] = pack_h2(s[0][2 * ks][0],     s[0][2 * ks][1]);
            a0[1] = pack_h2(s[0][2 * ks][2],     s[0][2 * ks][3]);
            a0[2] = pack_h2(s[0][2 * ks + 1][0], s[0][2 * ks + 1][1]);
            a0[3] = pack_h2(s[0][2 * ks + 1][2], s[0][2 * ks + 1][3]);
            a1[0] = pack_h2(s[1][2 * ks][0],     s[1][2 * ks][1]);
            a1[1] = pack_h2(s[1][2 * ks][2],     s[1][2 * ks][3]);
            a1[2] = pack_h2(s[1][2 * ks + 1][0], s[1][2 * ks + 1][1]);
            a1[3] = pack_h2(s[1][2 * ks + 1][2], s[1][2 * ks + 1][3]);
            #pragma unroll
            for (int ni = 0; ni < 8; ni++) {
                const uint32_t b0 = VT[(ks * 8 + t) * VSTR + ni * 8 + g];
                const uint32_t b1 = VT[(ks * 8 + 4 + t) * VSTR + ni * 8 + g];
                mma_f16(o[0][ni], a0, b0, b1);
                mma_f16(o[1][ni], a1, b0, b1);
            }
        }
        __syncthreads();   // next tile's buffer fully written; cur reads done
    }

    #pragma unroll
    for (int mi = 0; mi < 2; mi++) {
        const int mrow = wid * 32 + mi * 16 + g;
        const float inv0 = 1.f / lv[mi][0];
        const float inv1 = 1.f / lv[mi][1];
        const size_t r0 = (size_t)(b * S_ + q0 + mrow) * D_MODEL + h * HEAD_DIM;
        const size_t r1 = (size_t)(b * S_ + q0 + mrow + 8) * D_MODEL + h * HEAD_DIM;
        #pragma unroll
        for (int ni = 0; ni < 8; ni++) {
            const int col = ni * 8 + 2 * t;
            *(uint32_t*)&O[r0 + col] = pack_h2(o[mi][ni][0] * inv0, o[mi][ni][1] * inv0);
            *(uint32_t*)&O[r1 + col] = pack_h2(o[mi][ni][2] * inv1, o[mi][ni][3] * inv1);
        }
    }
}

// ---------------------------------------------------------------------------
// Residual add + LayerNorm; optional fp16 second output
// ---------------------------------------------------------------------------
__global__ __launch_bounds__(256)
void add_ln_kernel(const float* __restrict__ X,
                   const float* __restrict__ Y,
                   const float* __restrict__ g,
                   const float* __restrict__ beta,
                   float* __restrict__ out,
                   __half* __restrict__ outh)
{
    const int row = blockIdx.x;
    const int t = threadIdx.x;
    const float4 a = ((const float4*)(X + (size_t)row * D_MODEL))[t];
    const float4 c = ((const float4*)(Y + (size_t)row * D_MODEL))[t];
    const float v0 = a.x + c.x, v1 = a.y + c.y, v2 = a.z + c.z, v3 = a.w + c.w;

    float s  = v0 + v1 + v2 + v3;
    float ss = v0 * v0 + v1 * v1 + v2 * v2 + v3 * v3;

    #pragma unroll
    for (int off = 16; off; off >>= 1) {
        s  += __shfl_xor_sync(0xffffffffu, s,  off);
        ss += __shfl_xor_sync(0xffffffffu, ss, off);
    }
    __shared__ float ws[8], wss[8];
    const int w = t >> 5;
    if ((t & 31) == 0) { ws[w] = s; wss[w] = ss; }
    __syncthreads();

    float stot = 0.f, sstot = 0.f;
    #pragma unroll
    for (int i = 0; i < 8; i++) { stot += ws[i]; sstot += wss[i]; }

    const float mean = stot * (1.f / 1024.f);
    const float var  = sstot * (1.f / 1024.f) - mean * mean;
    const float r    = rsqrtf(var + 1e-5f);

    const float4 gg = ((const float4*)g)[t];
    const float4 bb = ((const float4*)beta)[t];
    float4 o;
    o.x = (v0 - mean) * r * gg.x + bb.x;
    o.y = (v1 - mean) * r * gg.y + bb.y;
    o.z = (v2 - mean) * r * gg.z + bb.z;
    o.w = (v3 - mean) * r * gg.w + bb.w;
    ((float4*)(out + (size_t)row * D_MODEL))[t] = o;
    if (outh) {
        uint2 q;
        q.x = pack_h2(o.x, o.y);
        q.y = pack_h2(o.z, o.w);
        ((uint2*)(outh + (size_t)row * D_MODEL))[t] = q;
    }
}

// ---------------------------------------------------------------------------
// Launch — attn_f16 in profiled slot #4
// ---------------------------------------------------------------------------
extern "C" void kernel_launch(void* const* d_in, const int* in_sizes, int n_in,
                              void* d_out, int out_size)
{
    const float* x    = (const float*)d_in[0];
    const int*   mask = (const int*)  d_in[1];
    const float* wq   = (const float*)d_in[2];
    const float* bq   = (const float*)d_in[3];
    const float* wk   = (const float*)d_in[4];
    const float* bk   = (const float*)d_in[5];
    const float* wv   = (const float*)d_in[6];
    const float* bv   = (const float*)d_in[7];
    const float* wo   = (const float*)d_in[8];
    const float* bo   = (const float*)d_in[9];
    const float* w1   = (const float*)d_in[10];
    const float* b1   = (const float*)d_in[11];
    const float* w2   = (const float*)d_in[12];
    const float* b2   = (const float*)d_in[13];
    const float* ln1g = (const float*)d_in[14];
    const float* ln1b = (const float*)d_in[15];
    const float* ln2g = (const float*)d_in[16];
    const float* ln2b = (const float*)d_in[17];

    __half *xh, *qkv, *ap, *x1h, *f1p;
    float *pp, *x1p, *f2p, *bqkv;
    __half *wqkvt, *wot, *w1t, *w2t;
    cudaGetSymbolAddress((void**)&xh,    g_xh);
    cudaGetSymbolAddress((void**)&qkv,   g_qkv);
    cudaGetSymbolAddress((void**)&ap,    g_attn);
    cudaGetSymbolAddress((void**)&pp,    g_proj);
    cudaGetSymbolAddress((void**)&x1p,   g_x1);
    cudaGetSymbolAddress((void**)&x1h,   g_x1h);
    cudaGetSymbolAddress((void**)&f1p,   g_ff1);
    cudaGetSymbolAddress((void**)&f2p,   g_ff2);
    cudaGetSymbolAddress((void**)&wqkvt, g_wqkvt);
    cudaGetSymbolAddress((void**)&wot,   g_wot);
    cudaGetSymbolAddress((void**)&w1t,   g_w1t);
    cudaGetSymbolAddress((void**)&w2t,   g_w2t);
    cudaGetSymbolAddress((void**)&bqkv,  g_bqkv);

    static int attr_set = 0;
    if (!attr_set) {
        cudaFuncSetAttribute(gemm_f16,
                             cudaFuncAttributeMaxDynamicSharedMemorySize,
                             GEMM_SMEM_BYTES);
        cudaFuncSetAttribute(gemm_f16,
                             cudaFuncAttributePreferredSharedMemoryCarveout,
                             cudaSharedmemCarveoutMaxShared);
        cudaFuncSetAttribute(attn_f16,
                             cudaFuncAttributeMaxDynamicSharedMemorySize,
                             ATTN_SMEM_BYTES);
        cudaFuncSetAttribute(attn_f16,
                             cudaFuncAttributePreferredSharedMemoryCarveout,
                             cudaSharedmemCarveoutMaxShared);
        attr_set = 1;
    }

    // 1-2: QKV GEMM dependencies
    prep_kernel<<<2060, 256>>>(x, xh, bq, bk, bv, bqkv);
    transpose3_kernel<<<dim3(32, 32, 3), 256>>>(wq, wk, wv, wqkvt);

    // 3: fused QKV GEMM
    gemm_f16<<<dim3(QKV_N / 128, ROWS / 128), 128, GEMM_SMEM_BYTES>>>(
        xh, wqkvt, bqkv, qkv, D_MODEL, QKV_N, 2);

    // 4 (profiled): attention — double-buffered
    attn_f16<<<dim3(S_ / 128, NUM_HEADS, B_), 128, ATTN_SMEM_BYTES>>>(
        qkv, mask, ap);

    transpose_h_kernel<<<dim3(D_MODEL / 32, D_MODEL / 32), 256>>>(wo, wot, D_MODEL, D_MODEL);
    transpose_h_kernel<<<dim3(D_FF / 32,    D_MODEL / 32), 256>>>(w1, w1t, D_MODEL, D_FF);
    transpose_h_kernel<<<dim3(D_MODEL / 32, D_FF / 32),    256>>>(w2, w2t, D_FF, D_MODEL);

    gemm_f16<<<dim3(D_MODEL / 128, ROWS / 128), 128, GEMM_SMEM_BYTES>>>(
        ap, wot, bo, pp, D_MODEL, D_MODEL, 0);
    add_ln_kernel<<<ROWS, 256>>>(x, pp, ln1g, ln1b, x1p, x1h);

    gemm_f16<<<dim3(D_FF / 128, ROWS / 128), 128, GEMM_SMEM_BYTES>>>(
        x1h, w1t, b1, f1p, D_MODEL, D_FF, 1);
    gemm_f16<<<dim3(D_MODEL / 128, ROWS / 128), 128, GEMM_SMEM_BYTES>>>(
        f1p, w2t, b2, f2p, D_FF, D_MODEL, 0);
    add_ln_kernel<<<ROWS, 256>>>(x1p, f2p, ln2g, ln2b, (float*)d_out, (__half*)0);
}

// round 17
// speedup vs baseline: 1.0725x; 1.0725x over previous
#include <cuda_runtime.h>
#include <cuda_fp16.h>
#include <cstdint>

#define D_MODEL   1024
#define NUM_HEADS 16
#define HEAD_DIM  64
#define D_FF      4096
#define B_        2
#define S_        2048
#define ROWS      (B_ * S_)   // 4096
#define QKV_N     (3 * D_MODEL)

// ---------------------------------------------------------------------------
// Scratch (device globals; no allocation allowed)
// ---------------------------------------------------------------------------
__device__ __half g_xh  [ROWS * D_MODEL];
__device__ __half g_qkv [ROWS * QKV_N];
__device__ __half g_attn[ROWS * D_MODEL];
__device__ float  g_proj[ROWS * D_MODEL];
__device__ float  g_x1  [ROWS * D_MODEL];
__device__ __half g_x1h [ROWS * D_MODEL];
__device__ __half g_ff1 [ROWS * D_FF];
__device__ float  g_ff2 [ROWS * D_MODEL];
__device__ __half g_wqkvt[QKV_N * D_MODEL];
__device__ __half g_wot  [D_MODEL * D_MODEL];
__device__ __half g_w1t  [D_FF * D_MODEL];
__device__ __half g_w2t  [D_MODEL * D_FF];
__device__ float  g_bqkv [QKV_N];

__device__ __forceinline__ uint32_t smem_u32(const void* p) {
    uint32_t a;
    asm("{ .reg .u64 t; cvta.to.shared.u64 t, %1; cvt.u32.u64 %0, t; }"
        : "=r"(a) : "l"(p));
    return a;
}
// fp16 mma m16n8k16, fp32 accum
__device__ __forceinline__ void mma_f16(float* d, const uint32_t* a,
                                        uint32_t b0, uint32_t b1) {
    asm volatile(
        "mma.sync.aligned.m16n8k16.row.col.f32.f16.f16.f32 "
        "{%0,%1,%2,%3}, {%4,%5,%6,%7}, {%8,%9}, {%0,%1,%2,%3};"
        : "+f"(d[0]), "+f"(d[1]), "+f"(d[2]), "+f"(d[3])
        : "r"(a[0]), "r"(a[1]), "r"(a[2]), "r"(a[3]), "r"(b0), "r"(b1));
}
#define LDSM_X4(R0, R1, R2, R3, saddr) \
    asm volatile("ldmatrix.sync.aligned.m8n8.x4.shared.b16 {%0,%1,%2,%3}, [%4];" \
        : "=r"(R0), "=r"(R1), "=r"(R2), "=r"(R3) : "r"(saddr))
#define LDSM_X4T(R0, R1, R2, R3, saddr) \
    asm volatile("ldmatrix.sync.aligned.m8n8.x4.trans.shared.b16 {%0,%1,%2,%3}, [%4];" \
        : "=r"(R0), "=r"(R1), "=r"(R2), "=r"(R3) : "r"(saddr))
#define CP16(dst, src) \
    asm volatile("cp.async.cg.shared.global [%0], [%1], 16;" \
                 :: "r"(dst), "l"(src) : "memory")
#define CP_COMMIT() asm volatile("cp.async.commit_group;" ::: "memory")
#define CP_WAITG1() asm volatile("cp.async.wait_group 1;" ::: "memory")
#define CP_WAITG0() asm volatile("cp.async.wait_group 0;" ::: "memory")

__device__ __forceinline__ uint32_t pack_h2(float lo, float hi) {
    __half2 h = __floats2half2_rn(lo, hi);
    return *(uint32_t*)&h;
}

// ---------------------------------------------------------------------------
// Weight prep
// ---------------------------------------------------------------------------
__global__ __launch_bounds__(256)
void transpose3_kernel(const float* __restrict__ wq, const float* __restrict__ wk,
                       const float* __restrict__ wv, __half* __restrict__ out)
{
    __shared__ float t[32][33];
    const float* W = (blockIdx.z == 0) ? wq : (blockIdx.z == 1) ? wk : wv;
    __half* Wt = out + (size_t)blockIdx.z * D_MODEL * D_MODEL;
    const int bn = blockIdx.x * 32;
    const int bk = blockIdx.y * 32;
    const int x = threadIdx.x & 31;
    const int y = (threadIdx.x >> 5) * 4;
    #pragma unroll
    for (int i = 0; i < 4; i++)
        t[y + i][x] = W[(size_t)(bk + y + i) * D_MODEL + bn + x];
    __syncthreads();
    #pragma unroll
    for (int i = 0; i < 4; i++)
        Wt[(size_t)(bn + y + i) * D_MODEL + bk + x] = __float2half(t[x][y + i]);
}

__global__ __launch_bounds__(256)
void transpose_h_kernel(const float* __restrict__ W, __half* __restrict__ Wt,
                        int Kd, int N)
{
    __shared__ float t[32][33];
    const int bn = blockIdx.x * 32;
    const int bk = blockIdx.y * 32;
    const int x = threadIdx.x & 31;
    const int y = (threadIdx.x >> 5) * 4;
    #pragma unroll
    for (int i = 0; i < 4; i++)
        t[y + i][x] = W[(size_t)(bk + y + i) * N + bn + x];
    __syncthreads();
    #pragma unroll
    for (int i = 0; i < 4; i++)
        Wt[(size_t)(bn + y + i) * Kd + bk + x] = __float2half(t[x][y + i]);
}

__global__ __launch_bounds__(256)
void prep_kernel(const float* __restrict__ in, __half* __restrict__ out,
                 const float* __restrict__ bq, const float* __restrict__ bk,
                 const float* __restrict__ bv, float* __restrict__ ob)
{
    const int bx = blockIdx.x;
    if (bx < 2048) {
        const int i = bx * 256 + threadIdx.x;
        float4 a = ((const float4*)in)[2 * i];
        float4 b = ((const float4*)in)[2 * i + 1];
        uint4 o;
        o.x = pack_h2(a.x, a.y); o.y = pack_h2(a.z, a.w);
        o.z = pack_h2(b.x, b.y); o.w = pack_h2(b.z, b.w);
        ((uint4*)out)[i] = o;
    } else {
        const int i = (bx - 2048) * 256 + threadIdx.x;
        float v = (i < 1024) ? bq[i] : (i < 2048) ? bk[i - 1024] : bv[i - 2048];
        ob[i] = v;
    }
}

// ---------------------------------------------------------------------------
// fp16 mma.sync GEMM (R13 3-stage pipeline — unchanged, proven).
// ---------------------------------------------------------------------------
#define GSTR 36
#define GOP  (128 * GSTR)
#define STGW (2 * GOP)
#define GEMM_SMEM_BYTES (3 * STGW * 4)    // 110592

__global__ __launch_bounds__(128)
void gemm_f16(const __half* __restrict__ A,
              const __half* __restrict__ Bt,
              const float* __restrict__ bias,
              void* __restrict__ Cv,
              int Kd, int N, int mode)
{
    extern __shared__ uint32_t smg[];
    const uint32_t sbase = smem_u32(smg);

    const int tid  = threadIdx.x;
    const int lane = tid & 31;
    const int wid  = tid >> 5;
    const int g = lane >> 2;
    const int t = lane & 3;
    const int wm = wid & 1;
    const int wn = wid >> 1;
    const int row0 = blockIdx.y * 128;
    const int col0 = blockIdx.x * 128;

    float acc[4][8][4];
    #pragma unroll
    for (int mi = 0; mi < 4; mi++)
        #pragma unroll
        for (int ni = 0; ni < 8; ni++)
            #pragma unroll
            for (int j = 0; j < 4; j++) acc[mi][ni][j] = 0.f;

    uint32_t sdst[8];
    const __half* aP[8];
    const __half* bP[8];
    #pragma unroll
    for (int i = 0; i < 8; i++) {
        const int slot = tid + i * 128;
        const int r = slot >> 3, q = slot & 7;
        sdst[i] = (uint32_t)(r * GSTR + q * 4) * 4u;
        aP[i] = A  + (size_t)(row0 + r) * Kd + q * 8;
        bP[i] = Bt + (size_t)(col0 + r) * Kd + q * 8;
    }

    const int lane7 = lane & 7;
    const uint32_t aRow  = (uint32_t)(wm * 64 + lane7 + (lane & 8));
    const uint32_t aColW = (uint32_t)((lane >> 4) * 4);
    const uint32_t aOffB = (aRow * GSTR + aColW) * 4u;
    const uint32_t bRow  = (uint32_t)(wn * 64 + lane7 + ((lane >> 4) & 1) * 8);
    const uint32_t bColW = (uint32_t)(((lane >> 3) & 1) * 4);
    const uint32_t bOffB = (bRow * GSTR + bColW) * 4u + GOP * 4u;

    const int NC = Kd >> 6;

    #pragma unroll
    for (int i = 0; i < 8; i++) {
        CP16(sbase + sdst[i], aP[i]);
        CP16(sbase + GOP * 4u + sdst[i], bP[i]);
    }
    CP_COMMIT();
    {
        const uint32_t st = (uint32_t)STGW * 4u;
        #pragma unroll
        for (int i = 0; i < 8; i++) {
            CP16(sbase + st + sdst[i], aP[i] + 64);
            CP16(sbase + st + GOP * 4u + sdst[i], bP[i] + 64);
        }
        CP_COMMIT();
    }

    for (int c = 0; c < NC; c++) {
        CP_WAITG1();
        __syncthreads();

        const uint32_t stg = sbase + (uint32_t)(c % 3) * ((uint32_t)STGW * 4u);
        const uint32_t aBase = stg + aOffB;
        const uint32_t bBase = stg + bOffB;

        #pragma unroll
        for (int ks = 0; ks < 4; ks++) {
            const uint32_t kOff = (uint32_t)(ks * 8) * 4u;
            uint32_t af[4][4];
            #pragma unroll
            for (int mi = 0; mi < 4; mi++) {
                LDSM_X4(af[mi][0], af[mi][1], af[mi][2], af[mi][3],
                        aBase + (uint32_t)(mi * 16 * GSTR) * 4u + kOff);
            }
            uint32_t bf[8][2];
            #pragma unroll
            for (int pr = 0; pr < 4; pr++) {
                LDSM_X4(bf[2 * pr][0], bf[2 * pr][1], bf[2 * pr + 1][0], bf[2 * pr + 1][1],
                        bBase + (uint32_t)(pr * 16 * GSTR) * 4u + kOff);
            }
            #pragma unroll
            for (int ni = 0; ni < 8; ni++)
                #pragma unroll
                for (int mi = 0; mi < 4; mi++)
                    mma_f16(acc[mi][ni], af[mi], bf[ni][0], bf[ni][1]);
        }

        if (c + 2 < NC) {
            const int ko = (c + 2) * 64;
            const uint32_t st = (uint32_t)((c + 2) % 3) * ((uint32_t)STGW * 4u);
            #pragma unroll
            for (int i = 0; i < 8; i++) {
                CP16(sbase + st + sdst[i], aP[i] + ko);
                CP16(sbase + st + GOP * 4u + sdst[i], bP[i] + ko);
            }
            CP_COMMIT();
        }
    }

    #pragma unroll
    for (int mi = 0; mi < 4; mi++) {
        const int r0 = row0 + wm * 64 + mi * 16 + g;
        #pragma unroll
        for (int ni = 0; ni < 8; ni++) {
            const int col = col0 + wn * 64 + ni * 8 + 2 * t;
            float2 bb = *(const float2*)&bias[col];
            float v00 = acc[mi][ni][0] + bb.x;
            float v01 = acc[mi][ni][1] + bb.y;
            float v10 = acc[mi][ni][2] + bb.x;
            float v11 = acc[mi][ni][3] + bb.y;
            if (mode == 0) {
                float* C = (float*)Cv;
                float2 o0 = {v00, v01}, o1 = {v10, v11};
                *(float2*)&C[(size_t)r0 * N + col]       = o0;
                *(float2*)&C[(size_t)(r0 + 8) * N + col] = o1;
            } else {
                if (mode == 1) {
                    v00 = fmaxf(v00, 0.f); v01 = fmaxf(v01, 0.f);
                    v10 = fmaxf(v10, 0.f); v11 = fmaxf(v11, 0.f);
                }
                __half* C = (__half*)Cv;
                *(uint32_t*)&C[(size_t)r0 * N + col]       = pack_h2(v00, v01);
                *(uint32_t*)&C[(size_t)(r0 + 8) * N + col] = pack_h2(v10, v11);
            }
        }
    }
}

// ---------------------------------------------------------------------------
// fp16 flash attention v5: 128 q/CTA, 32 q/warp, cp.async 3-stage K/V
// pipeline, K fragments via ldmatrix.x4, V fragments via ldmatrix.x4.trans
// (no zip). One __syncthreads per tile.
// Dynamic SMEM (words): Qs 128x44 @0; Ks 3x(64x36) @5632; Vs 3x(64x36)
// @12544; msb 3x2 @19456. Total 19462 words = 77848 B.
// ---------------------------------------------------------------------------
#define AST 44
#define KST 36
#define QS_OFF 0
#define KS_OFF 5632
#define VS_OFF 12544
#define MS_OFF 19456
#define KTW    (64 * KST)          // 2304 words per K/V buffer
#define ATTN_SMEM_BYTES (19462 * 4)

__global__ __launch_bounds__(128)
void attn_f16(const __half* __restrict__ QKV,
              const int*   __restrict__ mask,
              __half* __restrict__ O)
{
    extern __shared__ uint32_t sm[];
    const uint32_t sbase = smem_u32(sm);
    uint32_t* Qs = sm + QS_OFF;

    const int b  = blockIdx.z;
    const int h  = blockIdx.y;
    const int q0 = blockIdx.x * 128;
    const int tid  = threadIdx.x;
    const int lane = tid & 31;
    const int wid  = tid >> 5;
    const int g = lane >> 2;
    const int t = lane & 3;
    const int lane7 = lane & 7;

    const int qc = h * HEAD_DIM;
    const int kc = D_MODEL + h * HEAD_DIM;
    const int vc = 2 * D_MODEL + h * HEAD_DIM;

    // cp.async slot mapping: 64 rows x 8 16B-chunks = 512 slots; 4 per thread
    uint32_t cdst[4];
    int cro[4], cq8[4];
    #pragma unroll
    for (int i = 0; i < 4; i++) {
        const int slot = tid + i * 128;
        cro[i] = slot >> 3;
        cq8[i] = slot & 7;
        cdst[i] = (uint32_t)(cro[i] * KST + cq8[i] * 4) * 4u;
    }

    // ldmatrix lane offsets (bytes, within a buffer)
    const uint32_t kOffLane =
        ((uint32_t)(lane7 + ((lane >> 4) & 1) * 8) * KST +
         (uint32_t)(((lane >> 3) & 1) * 4)) * 4u;
    const uint32_t vOffLane =
        ((uint32_t)(lane7 + ((lane >> 3) & 1) * 8) * KST +
         (uint32_t)((lane >> 4) * 4)) * 4u;

    // tile loader: cp.async K+V rows + mask ballot into buffer bi
    auto load_tile = [&](int kt, int bi) {
        const uint32_t kb = sbase + (uint32_t)(KS_OFF + bi * KTW) * 4u;
        const uint32_t vb = sbase + (uint32_t)(VS_OFF + bi * KTW) * 4u;
        #pragma unroll
        for (int i = 0; i < 4; i++) {
            const __half* src = QKV + (size_t)(b * S_ + kt + cro[i]) * QKV_N + cq8[i] * 8;
            CP16(kb + cdst[i], src + kc);
            CP16(vb + cdst[i], src + vc);
        }
        if (tid < 64) {
            const int mv = mask[b * S_ + kt + tid];
            const uint32_t bits = __ballot_sync(0xffffffffu, mv != 0);
            if (lane == 0) sm[MS_OFF + bi * 2 + wid] = bits;
        }
    };

    // ---- Stage Q tile, extract fragments ----
    #pragma unroll
    for (int i = 0; i < 8; i++) {
        const int slot = tid + i * 128;
        const int r = slot >> 3, q8 = slot & 7;
        uint4 v = *(const uint4*)(QKV + (size_t)(b * S_ + q0 + r) * QKV_N + qc + q8 * 8);
        *(uint4*)&Qs[r * AST + q8 * 4] = v;
    }
    load_tile(0, 0);
    CP_COMMIT();
    __syncthreads();   // Q tile staged (regular stores) before fragment reads

    uint32_t qf[2][4][4];
    #pragma unroll
    for (int mi = 0; mi < 2; mi++) {
        const int mrow = wid * 32 + mi * 16 + g;
        #pragma unroll
        for (int ks = 0; ks < 4; ks++) {
            qf[mi][ks][0] = Qs[mrow * AST + ks * 8 + t];
            qf[mi][ks][1] = Qs[(mrow + 8) * AST + ks * 8 + t];
            qf[mi][ks][2] = Qs[mrow * AST + ks * 8 + 4 + t];
            qf[mi][ks][3] = Qs[(mrow + 8) * AST + ks * 8 + 4 + t];
        }
    }

    float o[2][8][4];
    #pragma unroll
    for (int mi = 0; mi < 2; mi++)
        #pragma unroll
        for (int ni = 0; ni < 8; ni++)
            #pragma unroll
            for (int j = 0; j < 4; j++) o[mi][ni][j] = 0.f;
    float mx[2][2] = {{-1e30f, -1e30f}, {-1e30f, -1e30f}};
    float lv[2][2] = {{0.f, 0.f}, {0.f, 0.f}};

    for (int kt = 0; kt < S_; kt += 64) {
        const int ti = kt >> 6;
        const int bi = ti % 3;
        if (kt + 64 < S_) {
            load_tile(kt + 64, (ti + 1) % 3);  // writes buffer != t-1's, != t's
            CP_COMMIT();
            CP_WAITG1();      // tile t's group complete; t+1 in flight
        } else {
            CP_WAITG0();
        }
        __syncthreads();      // cp data visible to all; t-1 reads done

        const uint32_t kb = sbase + (uint32_t)(KS_OFF + bi * KTW) * 4u;
        const uint32_t vb = sbase + (uint32_t)(VS_OFF + bi * KTW) * 4u;
        const uint32_t mw0 = sm[MS_OFF + bi * 2];
        const uint32_t mw1 = sm[MS_OFF + bi * 2 + 1];
        const bool allon = (mw0 & mw1) == 0xffffffffu;

        // S = Q @ K^T (K fragments via ldmatrix)
        float s[2][8][4];
        #pragma unroll
        for (int mi = 0; mi < 2; mi++)
            #pragma unroll
            for (int ni = 0; ni < 8; ni++)
                #pragma unroll
                for (int j = 0; j < 4; j++) s[mi][ni][j] = 0.f;

        #pragma unroll
        for (int ks = 0; ks < 4; ks++) {
            const uint32_t kOff = (uint32_t)(ks * 8) * 4u;
            uint32_t bf[8][2];
            #pragma unroll
            for (int pr = 0; pr < 4; pr++) {
                LDSM_X4(bf[2 * pr][0], bf[2 * pr][1],
                        bf[2 * pr + 1][0], bf[2 * pr + 1][1],
                        kb + kOffLane + (uint32_t)(pr * 16 * KST) * 4u + kOff);
            }
            #pragma unroll
            for (int ni = 0; ni < 8; ni++) {
                mma_f16(s[0][ni], qf[0][ks], bf[ni][0], bf[ni][1]);
                mma_f16(s[1][ni], qf[1][ks], bf[ni][0], bf[ni][1]);
            }
        }

        // scale + mask + online softmax
        bool k0a[8], k1a[8];
        if (!allon) {
            #pragma unroll
            for (int ni = 0; ni < 8; ni++) {
                const uint32_t word = (ni < 4) ? mw0 : mw1;
                const int shift = (ni & 3) * 8 + 2 * t;
                k0a[ni] = (word >> shift) & 1u;
                k1a[ni] = (word >> (shift + 1)) & 1u;
            }
        }

        #pragma unroll
        for (int mi = 0; mi < 2; mi++) {
            float rmax0 = -1e30f, rmax1 = -1e30f;
            #pragma unroll
            for (int ni = 0; ni < 8; ni++) {
                float v0 = s[mi][ni][0] * 0.125f;
                float v1 = s[mi][ni][1] * 0.125f;
                float v2 = s[mi][ni][2] * 0.125f;
                float v3 = s[mi][ni][3] * 0.125f;
                if (!allon) {
                    if (!k0a[ni]) { v0 = -1e9f; v2 = -1e9f; }
                    if (!k1a[ni]) { v1 = -1e9f; v3 = -1e9f; }
                }
                s[mi][ni][0] = v0; s[mi][ni][1] = v1;
                s[mi][ni][2] = v2; s[mi][ni][3] = v3;
                rmax0 = fmaxf(rmax0, fmaxf(v0, v1));
                rmax1 = fmaxf(rmax1, fmaxf(v2, v3));
            }
            rmax0 = fmaxf(rmax0, __shfl_xor_sync(0xffffffffu, rmax0, 1));
            rmax0 = fmaxf(rmax0, __shfl_xor_sync(0xffffffffu, rmax0, 2));
            rmax1 = fmaxf(rmax1, __shfl_xor_sync(0xffffffffu, rmax1, 1));
            rmax1 = fmaxf(rmax1, __shfl_xor_sync(0xffffffffu, rmax1, 2));

            const float mn0 = fmaxf(mx[mi][0], rmax0);
            const float mn1 = fmaxf(mx[mi][1], rmax1);
            const float c0 = __expf(mx[mi][0] - mn0);
            const float c1 = __expf(mx[mi][1] - mn1);

            float rs0 = 0.f, rs1 = 0.f;
            #pragma unroll
            for (int ni = 0; ni < 8; ni++) {
                float p0 = __expf(s[mi][ni][0] - mn0);
                float p1 = __expf(s[mi][ni][1] - mn0);
                float p2 = __expf(s[mi][ni][2] - mn1);
                float p3 = __expf(s[mi][ni][3] - mn1);
                s[mi][ni][0] = p0; s[mi][ni][1] = p1;
                s[mi][ni][2] = p2; s[mi][ni][3] = p3;
                rs0 += p0 + p1;
                rs1 += p2 + p3;
            }
            rs0 += __shfl_xor_sync(0xffffffffu, rs0, 1);
            rs0 += __shfl_xor_sync(0xffffffffu, rs0, 2);
            rs1 += __shfl_xor_sync(0xffffffffu, rs1, 1);
            rs1 += __shfl_xor_sync(0xffffffffu, rs1, 2);

            lv[mi][0] = lv[mi][0] * c0 + rs0;
            lv[mi][1] = lv[mi][1] * c1 + rs1;
            #pragma unroll
            for (int ni = 0; ni < 8; ni++) {
                o[mi][ni][0] *= c0; o[mi][ni][1] *= c0;
                o[mi][ni][2] *= c1; o[mi][ni][3] *= c1;
            }
            mx[mi][0] = mn0; mx[mi][1] = mn1;
        }

        // O += P @ V — register P; V fragments via ldmatrix.trans
        #pragma unroll
        for (int ks = 0; ks < 4; ks++) {
            uint32_t a0[4], a1[4];
            a0[0] = pack_h2(s[0][2 * ks][0],     s[0][2 * ks][1]);
            a0[1] = pack_h2(s[0][2 * ks][2],     s[0][2 * ks][3]);
            a0[2] = pack_h2(s[0][2 * ks + 1][0], s[0][2 * ks + 1][1]);
            a0[3] = pack_h2(s[0][2 * ks + 1][2], s[0][2 * ks + 1][3]);
            a1[0] = pack_h2(s[1][2 * ks][0],     s[1][2 * ks][1]);
            a1[1] = pack_h2(s[1][2 * ks][2],     s[1][2 * ks][3]);
            a1[2] = pack_h2(s[1][2 * ks + 1][0], s[1][2 * ks + 1][1]);
            a1[3] = pack_h2(s[1][2 * ks + 1][2], s[1][2 * ks + 1][3]);

            uint32_t vf[8][2];
            #pragma unroll
            for (int p = 0; p < 4; p++) {
                LDSM_X4T(vf[2 * p][0], vf[2 * p][1],
                         vf[2 * p + 1][0], vf[2 * p + 1][1],
                         vb + vOffLane + (uint32_t)(ks * 16 * KST) * 4u
                            + (uint32_t)(p * 8) * 4u);
            }
            #pragma unroll
            for (int ni = 0; ni < 8; ni++) {
                mma_f16(o[0][ni], a0, vf[ni][0], vf[ni][1]);
                mma_f16(o[1][ni], a1, vf[ni][0], vf[ni][1]);
            }
        }
    }

    #pragma unroll
    for (int mi = 0; mi < 2; mi++) {
        const int mrow = wid * 32 + mi * 16 + g;
        const float inv0 = 1.f / lv[mi][0];
        const float inv1 = 1.f / lv[mi][1];
        const size_t r0 = (size_t)(b * S_ + q0 + mrow) * D_MODEL + h * HEAD_DIM;
        const size_t r1 = (size_t)(b * S_ + q0 + mrow + 8) * D_MODEL + h * HEAD_DIM;
        #pragma unroll
        for (int ni = 0; ni < 8; ni++) {
            const int col = ni * 8 + 2 * t;
            *(uint32_t*)&O[r0 + col] = pack_h2(o[mi][ni][0] * inv0, o[mi][ni][1] * inv0);
            *(uint32_t*)&O[r1 + col] = pack_h2(o[mi][ni][2] * inv1, o[mi][ni][3] * inv1);
        }
    }
}

// ---------------------------------------------------------------------------
// Residual add + LayerNorm; optional fp16 second output
// ---------------------------------------------------------------------------
__global__ __launch_bounds__(256)
void add_ln_kernel(const float* __restrict__ X,
                   const float* __restrict__ Y,
                   const float* __restrict__ g,
                   const float* __restrict__ beta,
                   float* __restrict__ out,
                   __half* __restrict__ outh)
{
    const int row = blockIdx.x;
    const int t = threadIdx.x;
    const float4 a = ((const float4*)(X + (size_t)row * D_MODEL))[t];
    const float4 c = ((const float4*)(Y + (size_t)row * D_MODEL))[t];
    const float v0 = a.x + c.x, v1 = a.y + c.y, v2 = a.z + c.z, v3 = a.w + c.w;

    float s  = v0 + v1 + v2 + v3;
    float ss = v0 * v0 + v1 * v1 + v2 * v2 + v3 * v3;

    #pragma unroll
    for (int off = 16; off; off >>= 1) {
        s  += __shfl_xor_sync(0xffffffffu, s,  off);
        ss += __shfl_xor_sync(0xffffffffu, ss, off);
    }
    __shared__ float ws[8], wss[8];
    const int w = t >> 5;
    if ((t & 31) == 0) { ws[w] = s; wss[w] = ss; }
    __syncthreads();

    float stot = 0.f, sstot = 0.f;
    #pragma unroll
    for (int i = 0; i < 8; i++) { stot += ws[i]; sstot += wss[i]; }

    const float mean = stot * (1.f / 1024.f);
    const float var  = sstot * (1.f / 1024.f) - mean * mean;
    const float r    = rsqrtf(var + 1e-5f);

    const float4 gg = ((const float4*)g)[t];
    const float4 bb = ((const float4*)beta)[t];
    float4 o;
    o.x = (v0 - mean) * r * gg.x + bb.x;
    o.y = (v1 - mean) * r * gg.y + bb.y;
    o.z = (v2 - mean) * r * gg.z + bb.z;
    o.w = (v3 - mean) * r * gg.w + bb.w;
    ((float4*)(out + (size_t)row * D_MODEL))[t] = o;
    if (outh) {
        uint2 q;
        q.x = pack_h2(o.x, o.y);
        q.y = pack_h2(o.z, o.w);
        ((uint2*)(outh + (size_t)row * D_MODEL))[t] = q;
    }
}

// ---------------------------------------------------------------------------
// Launch — attn_f16 in profiled slot #4
// ---------------------------------------------------------------------------
extern "C" void kernel_launch(void* const* d_in, const int* in_sizes, int n_in,
                              void* d_out, int out_size)
{
    const float* x    = (const float*)d_in[0];
    const int*   mask = (const int*)  d_in[1];
    const float* wq   = (const float*)d_in[2];
    const float* bq   = (const float*)d_in[3];
    const float* wk   = (const float*)d_in[4];
    const float* bk   = (const float*)d_in[5];
    const float* wv   = (const float*)d_in[6];
    const float* bv   = (const float*)d_in[7];
    const float* wo   = (const float*)d_in[8];
    const float* bo   = (const float*)d_in[9];
    const float* w1   = (const float*)d_in[10];
    const float* b1   = (const float*)d_in[11];
    const float* w2   = (const float*)d_in[12];
    const float* b2   = (const float*)d_in[13];
    const float* ln1g = (const float*)d_in[14];
    const float* ln1b = (const float*)d_in[15];
    const float* ln2g = (const float*)d_in[16];
    const float* ln2b = (const float*)d_in[17];

    __half *xh, *qkv, *ap, *x1h, *f1p;
    float *pp, *x1p, *f2p, *bqkv;
    __half *wqkvt, *wot, *w1t, *w2t;
    cudaGetSymbolAddress((void**)&xh,    g_xh);
    cudaGetSymbolAddress((void**)&qkv,   g_qkv);
    cudaGetSymbolAddress((void**)&ap,    g_attn);
    cudaGetSymbolAddress((void**)&pp,    g_proj);
    cudaGetSymbolAddress((void**)&x1p,   g_x1);
    cudaGetSymbolAddress((void**)&x1h,   g_x1h);
    cudaGetSymbolAddress((void**)&f1p,   g_ff1);
    cudaGetSymbolAddress((void**)&f2p,   g_ff2);
    cudaGetSymbolAddress((void**)&wqkvt, g_wqkvt);
    cudaGetSymbolAddress((void**)&wot,   g_wot);
    cudaGetSymbolAddress((void**)&w1t,   g_w1t);
    cudaGetSymbolAddress((void**)&w2t,   g_w2t);
    cudaGetSymbolAddress((void**)&bqkv,  g_bqkv);

    static int attr_set = 0;
    if (!attr_set) {
        cudaFuncSetAttribute(gemm_f16,
                             cudaFuncAttributeMaxDynamicSharedMemorySize,
                             GEMM_SMEM_BYTES);
        cudaFuncSetAttribute(gemm_f16,
                             cudaFuncAttributePreferredSharedMemoryCarveout,
                             cudaSharedmemCarveoutMaxShared);
        cudaFuncSetAttribute(attn_f16,
                             cudaFuncAttributeMaxDynamicSharedMemorySize,
                             ATTN_SMEM_BYTES);
        cudaFuncSetAttribute(attn_f16,
                             cudaFuncAttributePreferredSharedMemoryCarveout,
                             cudaSharedmemCarveoutMaxShared);
        attr_set = 1;
    }

    // 1-2: QKV GEMM dependencies
    prep_kernel<<<2060, 256>>>(x, xh, bq, bk, bv, bqkv);
    transpose3_kernel<<<dim3(32, 32, 3), 256>>>(wq, wk, wv, wqkvt);

    // 3: fused QKV GEMM
    gemm_f16<<<dim3(QKV_N / 128, ROWS / 128), 128, GEMM_SMEM_BYTES>>>(
        xh, wqkvt, bqkv, qkv, D_MODEL, QKV_N, 2);

    // 4 (profiled): attention — cp.async pipelined, ldmatrix fragments
    attn_f16<<<dim3(S_ / 128, NUM_HEADS, B_), 128, ATTN_SMEM_BYTES>>>(
        qkv, mask, ap);

    transpose_h_kernel<<<dim3(D_MODEL / 32, D_MODEL / 32), 256>>>(wo, wot, D_MODEL, D_MODEL);
    transpose_h_kernel<<<dim3(D_FF / 32,    D_MODEL / 32), 256>>>(w1, w1t, D_MODEL, D_FF);
    transpose_h_kernel<<<dim3(D_MODEL / 32, D_FF / 32),    256>>>(w2, w2t, D_FF, D_MODEL);

    gemm_f16<<<dim3(D_MODEL / 128, ROWS / 128), 128, GEMM_SMEM_BYTES>>>(
        ap, wot, bo, pp, D_MODEL, D_MODEL, 0);
    add_ln_kernel<<<ROWS, 256>>>(x, pp, ln1g, ln1b, x1p, x1h);

    gemm_f16<<<dim3(D_FF / 128, ROWS / 128), 128, GEMM_SMEM_BYTES>>>(
        x1h, w1t, b1, f1p, D_MODEL, D_FF, 1);
    gemm_f16<<<dim3(D_MODEL / 128, ROWS / 128), 128, GEMM_SMEM_BYTES>>>(
        f1p, w2t, b2, f2p, D_FF, D_MODEL, 0);
    add_ln_kernel<<<ROWS, 256>>>(x1p, f2p, ln2g, ln2b, (float*)d_out, (__half*)0);
}